// round 16
// baseline (speedup 1.0000x reference)
#include <cuda_runtime.h>
#include <cuda_bf16.h>
#include <cuda_fp16.h>
#include <math_constants.h>
#include <cstdint>

#define BN 4
#define TT 512
#define SS 512
#define IND 512
#define MD 256

// Scratch (allocation-free rule: __device__ globals)
__device__ float g_wq[BN * TT * MD];            // [b*T+t][d]
__device__ float g_uht[BN * MD * SS];           // [b][d][s]  (transposed uh)
__device__ float g_ctxp[2][BN * TT * MD];       // ctx split-K partials
__device__ float g_align_scratch[BN * TT * SS];
// bf16-split packed operands (per element 1 u32; pair p -> u32 2p=hi, 2p+1=lo)
__device__ uint32_t g_apk[BN * TT * 768];       // A(out) = concat(c, inputs)
__device__ uint32_t g_wpk[IND * 768];           // Wout
__device__ uint32_t g_wqpk[MD * 512];           // Wq
__device__ uint32_t g_wcpk[MD * 256];           // Wc
__device__ uint32_t g_mpk[BN * SS * 256];       // mems  [row][k=m]  (proj A)
__device__ uint32_t g_mtpk[BN * 256 * 512];     // mems^T [b][m][k=s] (ctx B)
__device__ uint32_t g_ppk[BN * TT * 512];       // P probabilities [row][k=s]

__device__ __forceinline__ uint32_t pack_bf2(float x0, float x1) {
    __nv_bfloat162 h = __floats2bfloat162_rn(x0, x1);
    return *reinterpret_cast<uint32_t*>(&h);
}

__device__ __forceinline__ void split2(float x0, float x1,
                                       uint32_t& hi, uint32_t& lo) {
    const float h0 = __bfloat162float(__float2bfloat16_rn(x0));
    const float h1 = __bfloat162float(__float2bfloat16_rn(x1));
    hi = pack_bf2(h0, h1);
    lo = pack_bf2(x0 - h0, x1 - h1);
}

// packed-half tanh: 2 elements per MUFU op
__device__ __forceinline__ float2 tanh2(float x, float y) {
    __half2 h = __floats2half2_rn(x, y);
    uint32_t u = *reinterpret_cast<uint32_t*>(&h);
    asm("tanh.approx.f16x2 %0, %0;" : "+r"(u));
    __half2 r = *reinterpret_cast<__half2*>(&u);
    return __half22float2(r);
}

__device__ __forceinline__ void mma_bf(float* cc,
    uint32_t a0, uint32_t a1, uint32_t a2, uint32_t a3,
    uint32_t b0, uint32_t b1)
{
    asm volatile(
        "mma.sync.aligned.m16n8k16.row.col.f32.bf16.bf16.f32 "
        "{%0,%1,%2,%3},{%4,%5,%6,%7},{%8,%9},{%0,%1,%2,%3};"
        : "+f"(cc[0]), "+f"(cc[1]), "+f"(cc[2]), "+f"(cc[3])
        : "r"(a0), "r"(a1), "r"(a2), "r"(a3), "r"(b0), "r"(b1));
}

// ---------------------------------------------------------------------------
// cvt_pre: ALL static packing in one launch (flat-index regions).
// ---------------------------------------------------------------------------
__global__ __launch_bounds__(256) void cvt_pre(
    const float* __restrict__ inputs, const float* __restrict__ mems,
    const float* __restrict__ Wq, const float* __restrict__ Wc,
    const float* __restrict__ Wout)
{
    int idx = blockIdx.x * 256 + threadIdx.x;
    uint32_t hi, lo;
    if (idx < 196608) {                       // R0: Wout
        const int row = idx / 384, p = idx % 384;
        split2(Wout[row * 768 + 2 * p], Wout[row * 768 + 2 * p + 1], hi, lo);
        g_wpk[row * 768 + 2 * p] = hi;
        g_wpk[row * 768 + 2 * p + 1] = lo;
        return;
    }
    idx -= 196608;
    if (idx < 524288) {                       // R1: inputs
        const int row = idx >> 8, q = idx & 255;
        split2(inputs[row * 512 + 2 * q], inputs[row * 512 + 2 * q + 1], hi, lo);
        g_apk[row * 768 + 256 + 2 * q] = hi;
        g_apk[row * 768 + 256 + 2 * q + 1] = lo;
        return;
    }
    idx -= 524288;
    if (idx < 65536) {                        // R2: Wq
        const int row = idx >> 8, p = idx & 255;
        split2(Wq[row * 512 + 2 * p], Wq[row * 512 + 2 * p + 1], hi, lo);
        g_wqpk[row * 512 + 2 * p] = hi;
        g_wqpk[row * 512 + 2 * p + 1] = lo;
        return;
    }
    idx -= 65536;
    if (idx < 32768) {                        // R3: Wc
        const int row = idx >> 7, p = idx & 127;
        split2(Wc[row * 256 + 2 * p], Wc[row * 256 + 2 * p + 1], hi, lo);
        g_wcpk[row * 256 + 2 * p] = hi;
        g_wcpk[row * 256 + 2 * p + 1] = lo;
        return;
    }
    idx -= 32768;
    if (idx < 262144) {                       // R4: mems (proj A layout)
        const int row = idx >> 7, p = idx & 127;
        split2(mems[row * 256 + 2 * p], mems[row * 256 + 2 * p + 1], hi, lo);
        g_mpk[row * 256 + 2 * p] = hi;
        g_mpk[row * 256 + 2 * p + 1] = lo;
        return;
    }
    idx -= 262144;
    {                                         // R5: mems^T (ctx B layout)
        const int b = idx >> 16;
        const int m = (idx >> 8) & 255;
        const int p = idx & 255;
        const float x0 = mems[b * 131072 + (2 * p) * 256 + m];
        const float x1 = mems[b * 131072 + (2 * p + 1) * 256 + m];
        split2(x0, x1, hi, lo);
        g_mtpk[b * 131072 + m * 512 + 2 * p] = hi;
        g_mtpk[b * 131072 + m * 512 + 2 * p + 1] = lo;
    }
}

// ===========================================================================
// Shared 64x64 bf16x3 mma tile machinery (256 thr, 8 warps = 2m x 4n,
// warp tile 32m x 16n, frags c[2 m16][2 n8][4]).  smem pitch 20 u32.
// ===========================================================================
#define MMA_TILE_BODY(ABASE, ASTR, BBASE, BSTR, NIT)                          \
    const int ar0 = tid >> 2, as0 = (tid & 3) * 4;                            \
    uint4 ra0, rb;                                                            \
    auto ldTile = [&](int it) {                                               \
        const int ko = it * 16;                                               \
        ra0 = *(const uint4*)&(ABASE)[(size_t)(bm + ar0) * (ASTR) + ko + as0];\
        rb  = *(const uint4*)&(BBASE)[(size_t)(bn + ar0) * (BSTR) + ko + as0];\
    };                                                                        \
    auto stTile = [&](int bf_) {                                              \
        *(uint4*)&Ash[bf_][ar0 * 20 + as0] = ra0;                             \
        *(uint4*)&Bsh[bf_][ar0 * 20 + as0] = rb;                              \
    };                                                                        \
    ldTile(0);                                                                \
    stTile(0);                                                                \
    __syncthreads();                                                          \
    int buf = 0;                                                              \
    for (int it = 0; it < (NIT); it++) {                                      \
        const bool more = (it + 1 < (NIT));                                   \
        if (more) ldTile(it + 1);                                             \
        const uint32_t* Ab = Ash[buf] + (wm * 32) * 20;                       \
        const uint32_t* Bb = Bsh[buf] + (wn * 16) * 20;                       \
        uint2 af[2][4];                                                       \
        _Pragma("unroll")                                                     \
        for (int m2 = 0; m2 < 2; m2++) {                                      \
            const int r0 = m2 * 16 + g;                                       \
            af[m2][0] = *(const uint2*)&Ab[r0 * 20 + t * 2];                  \
            af[m2][1] = *(const uint2*)&Ab[(r0 + 8) * 20 + t * 2];            \
            af[m2][2] = *(const uint2*)&Ab[r0 * 20 + t * 2 + 8];              \
            af[m2][3] = *(const uint2*)&Ab[(r0 + 8) * 20 + t * 2 + 8];        \
        }                                                                     \
        uint2 bfr[2][2];                                                      \
        _Pragma("unroll")                                                     \
        for (int n2 = 0; n2 < 2; n2++) {                                      \
            const int rn = n2 * 8 + g;                                        \
            bfr[n2][0] = *(const uint2*)&Bb[rn * 20 + t * 2];                 \
            bfr[n2][1] = *(const uint2*)&Bb[rn * 20 + t * 2 + 8];             \
        }                                                                     \
        _Pragma("unroll")                                                     \
        for (int m2 = 0; m2 < 2; m2++)                                        \
            _Pragma("unroll")                                                 \
            for (int n2 = 0; n2 < 2; n2++) {                                  \
                float* cc = c[m2][n2];                                        \
                mma_bf(cc, af[m2][0].x, af[m2][1].x, af[m2][2].x,             \
                       af[m2][3].x, bfr[n2][0].x, bfr[n2][1].x);              \
                mma_bf(cc, af[m2][0].y, af[m2][1].y, af[m2][2].y,             \
                       af[m2][3].y, bfr[n2][0].x, bfr[n2][1].x);              \
                mma_bf(cc, af[m2][0].x, af[m2][1].x, af[m2][2].x,             \
                       af[m2][3].x, bfr[n2][0].y, bfr[n2][1].y);              \
            }                                                                 \
        if (more) stTile(buf ^ 1);                                            \
        __syncthreads();                                                      \
        buf ^= 1;                                                             \
    }

#define MMA_TILE_PREAMBLE                                                     \
    __shared__ uint32_t Ash[2][64 * 20];                                      \
    __shared__ uint32_t Bsh[2][64 * 20];                                      \
    const int tid = threadIdx.x;                                              \
    const int lane = tid & 31;                                                \
    const int warp = tid >> 5;                                                \
    const int wm = warp >> 2, wn = warp & 3;                                  \
    const int g = lane >> 2, t = lane & 3;                                    \
    float c[2][2][4];                                                         \
    _Pragma("unroll")                                                         \
    for (int m2 = 0; m2 < 2; m2++)                                            \
        _Pragma("unroll")                                                     \
        for (int n2 = 0; n2 < 2; n2++)                                        \
            _Pragma("unroll")                                                 \
            for (int q = 0; q < 4; q++) c[m2][n2][q] = 0.f;

// ---------------------------------------------------------------------------
// proj_mma: z=0: g_wq = inputs @ Wq^T (K=512); z=1: g_uht (transposed) + bc.
// Grid (4, 32, 2) = 256 blocks.
// ---------------------------------------------------------------------------
__global__ __launch_bounds__(256) void proj_mma(const float* __restrict__ bc)
{
    MMA_TILE_PREAMBLE
    const int bm = blockIdx.y * 64;
    const int bn = blockIdx.x * 64;
    const int z = blockIdx.z;

    const uint32_t* Abase = z ? g_mpk : (g_apk + 256);
    const int astr = z ? 256 : 768;
    const uint32_t* Bbase = z ? g_wcpk : g_wqpk;
    const int bstr = z ? 256 : 512;
    const int NIT = z ? 16 : 32;

    MMA_TILE_BODY(Abase, astr, Bbase, bstr, NIT)

    if (z == 0) {
#pragma unroll
        for (int m2 = 0; m2 < 2; m2++) {
            const int r0 = bm + wm * 32 + m2 * 16 + g;
#pragma unroll
            for (int n2 = 0; n2 < 2; n2++) {
                const int col = bn + wn * 16 + n2 * 8 + t * 2;
                float* cc = c[m2][n2];
                *(float2*)&g_wq[r0 * MD + col] = make_float2(cc[0], cc[1]);
                *(float2*)&g_wq[(r0 + 8) * MD + col] = make_float2(cc[2], cc[3]);
            }
        }
    } else {
        const int b_ = bm >> 9;
        float* base = g_uht + b_ * (MD * SS);
#pragma unroll
        for (int m2 = 0; m2 < 2; m2++) {
            const int r0 = bm + wm * 32 + m2 * 16 + g;
            const int s0 = r0 & 511, s1 = (r0 + 8) & 511;
#pragma unroll
            for (int n2 = 0; n2 < 2; n2++) {
                const int col = bn + wn * 16 + n2 * 8 + t * 2;
                const float b0v = bc[col], b1v = bc[col + 1];
                float* cc = c[m2][n2];
                base[col * SS + s0] = cc[0] + b0v;
                base[(col + 1) * SS + s0] = cc[1] + b1v;
                base[col * SS + s1] = cc[2] + b0v;
                base[(col + 1) * SS + s1] = cc[3] + b1v;
            }
        }
    }
}

// ---------------------------------------------------------------------------
// align_kernel: 64-s chunks, 16-t tiles. tanh via f16x2 MUFU (2 elem/op):
// halves the MUFU floor (66.6 -> 33.3 us chip). Args computed in f32,
// accumulation in f32 (only tanh eval in half precision).
// ---------------------------------------------------------------------------
__global__ __launch_bounds__(256) void align_kernel(
    const int* __restrict__ mem_masks, const float* __restrict__ v,
    float* __restrict__ pa)
{
    const int b = blockIdx.z;
    const int t0 = blockIdx.y * 16;
    const int c = blockIdx.x;
    const int len = mem_masks[b];
    if (c * 64 >= len) return;

    extern __shared__ float sh[];
    float* uh_sh = sh;                 // [256 d][64 s]
    float* wq_sh = sh + 256 * 64;      // [16][256]
    float* v_sh  = wq_sh + 16 * 256;   // [256]

    const int tid = threadIdx.x;
    const int lane = tid & 31;
    const int warp = tid >> 5;

    {
        const float* src = g_wq + (b * TT + t0) * MD;
        for (int i = tid; i < (16 * 256) / 4; i += 256)
            *(float4*)&wq_sh[i * 4] = *(const float4*)&src[i * 4];
        if (tid < 64)
            *(float4*)&v_sh[tid * 4] = *(const float4*)&v[tid * 4];
        const float* usrc = g_uht + b * (MD * SS) + c * 64;
        for (int i = tid; i < 256 * 16; i += 256) {
            const int d = i >> 4, g = i & 15;
            *(float4*)&uh_sh[d * 64 + g * 4] =
                *(const float4*)&usrc[d * SS + g * 4];
        }
    }
    __syncthreads();

    const int ta = warp * 2;
    const float* wq0 = wq_sh + ta * 256;
    const float* wq1 = wq0 + 256;
    const int sl = lane * 2;
    float2 a0 = make_float2(0.f, 0.f);
    float2 a1 = make_float2(0.f, 0.f);
#pragma unroll 8
    for (int d = 0; d < 256; d++) {
        float2 u = *(float2*)&uh_sh[d * 64 + sl];
        float w0 = wq0[d], w1 = wq1[d], vd = v_sh[d];
        float2 t0 = tanh2(u.x + w0, u.y + w0);
        float2 t1 = tanh2(u.x + w1, u.y + w1);
        a0.x += vd * t0.x;
        a0.y += vd * t0.y;
        a1.x += vd * t1.x;
        a1.y += vd * t1.y;
    }
    const int sg = c * 64 + sl;
    *(float2*)&pa[(b * TT + t0 + ta) * SS + sg] = a0;
    *(float2*)&pa[(b * TT + t0 + ta + 1) * SS + sg] = a1;
}

// ---------------------------------------------------------------------------
// softmax_kernel: warp per t-row; fp32 probs -> pa, packed bf16 hi/lo -> g_ppk.
// ---------------------------------------------------------------------------
__global__ __launch_bounds__(256) void softmax_kernel(
    const int* __restrict__ mem_masks, float* __restrict__ pa)
{
    const int lane = threadIdx.x & 31;
    const int warp = threadIdx.x >> 5;
    const int row = blockIdx.x * 8 + warp;
    const int b = row >> 9;
    const int len = mem_masks[b];
    float* prow = pa + row * SS;
    const float NEG = -CUDART_INF_F;

    float vals[16];
    float mx = NEG;
#pragma unroll
    for (int k = 0; k < 16; k++) {
        const int s = lane + k * 32;
        const float val = (s < len) ? prow[s] : NEG;
        vals[k] = val;
        mx = fmaxf(mx, val);
    }
#pragma unroll
    for (int o = 16; o; o >>= 1) mx = fmaxf(mx, __shfl_xor_sync(~0u, mx, o));
    float sum = 0.f;
#pragma unroll
    for (int k = 0; k < 16; k++) {
        const int s = lane + k * 32;
        const float e = (s < len) ? __expf(vals[k] - mx) : 0.f;
        vals[k] = e;
        sum += e;
    }
#pragma unroll
    for (int o = 16; o; o >>= 1) sum += __shfl_xor_sync(~0u, sum, o);
    const float inv = 1.0f / sum;
#pragma unroll
    for (int k = 0; k < 16; k++) {
        const float p = vals[k] * inv;
        prow[lane + k * 32] = p;
        const float pp = __shfl_xor_sync(~0u, p, 1);
        if ((lane & 1) == 0) {
            uint32_t hi, lo;
            split2(p, pp, hi, lo);
            *(uint2*)&g_ppk[row * 512 + lane + k * 32] = make_uint2(hi, lo);
        }
    }
}

// ---------------------------------------------------------------------------
// ctx_mma: split-K=2 over s (len-trimmed). Grid (4, 8, 8) = 256 blocks.
// ---------------------------------------------------------------------------
__global__ __launch_bounds__(256) void ctx_mma(const int* __restrict__ mem_masks)
{
    MMA_TILE_PREAMBLE
    const int b = blockIdx.z >> 1;
    const int kc = blockIdx.z & 1;
    const int bm = blockIdx.y * 64;       // t within b
    const int bn = blockIdx.x * 64;       // m

    const int len = mem_masks[b];
    int rem = len - kc * 256;
    if (rem > 256) rem = 256;
    const int NIT = (rem > 0) ? ((rem + 15) >> 4) : 0;

    const uint32_t* Abase = g_ppk + (b * TT) * 512 + kc * 256;
    const uint32_t* Bbase = g_mtpk + b * (256 * 512) + kc * 256;

    if (NIT > 0) {
        MMA_TILE_BODY(Abase, 512, Bbase, 512, NIT)
    }

    float* dst = g_ctxp[kc];
#pragma unroll
    for (int m2 = 0; m2 < 2; m2++) {
        const int r0 = b * TT + bm + wm * 32 + m2 * 16 + g;
#pragma unroll
        for (int n2 = 0; n2 < 2; n2++) {
            const int col = bn + wn * 16 + n2 * 8 + t * 2;
            float* cc = c[m2][n2];
            *(float2*)&dst[r0 * MD + col] = make_float2(cc[0], cc[1]);
            *(float2*)&dst[(r0 + 8) * MD + col] = make_float2(cc[2], cc[3]);
        }
    }
}

// ---------------------------------------------------------------------------
// cvt_c: fold ctx partials + convert -> packed A k-region [0,256).
// ---------------------------------------------------------------------------
__global__ __launch_bounds__(256) void cvt_c()
{
    const int idx = blockIdx.x * 256 + threadIdx.x;   // 2048*128
    const int row = idx >> 7, q = idx & 127;
    const int e = row * 256 + 2 * q;
    const float x0 = g_ctxp[0][e] + g_ctxp[1][e];
    const float x1 = g_ctxp[0][e + 1] + g_ctxp[1][e + 1];
    uint32_t hi, lo;
    split2(x0, x1, hi, lo);
    const int base = row * 768 + 2 * q;
    g_apk[base] = hi;
    g_apk[base + 1] = lo;
}

// ---------------------------------------------------------------------------
// out_mma: attn_h = A @ Wout^T + bout. Grid (8, 32) = 256 blocks, 48 iters.
// ---------------------------------------------------------------------------
__global__ __launch_bounds__(256) void out_mma(
    const float* __restrict__ bout, float* __restrict__ out)
{
    MMA_TILE_PREAMBLE
    const int bm = blockIdx.y * 64;
    const int bn = blockIdx.x * 64;

    MMA_TILE_BODY(g_apk, 768, g_wpk, 768, 48)

#pragma unroll
    for (int m2 = 0; m2 < 2; m2++) {
        const int r0 = bm + wm * 32 + m2 * 16 + g;
#pragma unroll
        for (int n2 = 0; n2 < 2; n2++) {
            const int col = bn + wn * 16 + n2 * 8 + t * 2;
            const float2 bb = *(const float2*)&bout[col];
            float* cc = c[m2][n2];
            *(float2*)&out[r0 * IND + col] =
                make_float2(cc[0] + bb.x, cc[1] + bb.y);
            *(float2*)&out[(r0 + 8) * IND + col] =
                make_float2(cc[2] + bb.x, cc[3] + bb.y);
        }
    }
}

// ---------------------------------------------------------------------------
extern "C" void kernel_launch(void* const* d_in, const int* in_sizes, int n_in,
                              void* d_out, int out_size)
{
    const float* inputs    = (const float*)d_in[0];
    const float* mems      = (const float*)d_in[1];
    const int*   mem_masks = (const int*)d_in[2];
    const float* Wq        = (const float*)d_in[3];
    const float* Wc        = (const float*)d_in[4];
    const float* bc        = (const float*)d_in[5];
    const float* v         = (const float*)d_in[6];
    const float* Wout      = (const float*)d_in[7];
    const float* bout      = (const float*)d_in[8];

    float* out = (float*)d_out;
    float* pa;
    if (out_size >= BN * TT * IND + BN * TT * SS) {
        pa = out + BN * TT * IND;  // align written in-place in the output
    } else {
        cudaGetSymbolAddress((void**)&pa, g_align_scratch);
    }

    const size_t SMEM_ALIGN = (size_t)(256 * 64 + 16 * 256 + 256) * sizeof(float);
    cudaFuncSetAttribute(align_kernel,
                         cudaFuncAttributeMaxDynamicSharedMemorySize, (int)SMEM_ALIGN);

    cvt_pre<<<5248, 256>>>(inputs, mems, Wq, Wc, Wout);
    proj_mma<<<dim3(4, 32, 2), 256>>>(bc);
    align_kernel<<<dim3(8, 32, 4), 256, SMEM_ALIGN>>>(mem_masks, v, pa);
    softmax_kernel<<<256, 256>>>(mem_masks, pa);
    ctx_mma<<<dim3(4, 8, 8), 256>>>(mem_masks);
    cvt_c<<<1024, 256>>>();
    out_mma<<<dim3(8, 32), 256>>>(bout, out);
}

// round 17
// speedup vs baseline: 1.0008x; 1.0008x over previous
#include <cuda_runtime.h>
#include <cuda_bf16.h>
#include <math_constants.h>
#include <cstdint>

#define BN 4
#define TT 512
#define SS 512
#define IND 512
#define MD 256

// Scratch (allocation-free rule: __device__ globals)
__device__ float g_wq[BN * TT * MD];            // [b*T+t][d]
__device__ float g_uht[BN * MD * SS];           // [b][d][s]  (transposed uh)
__device__ float g_align_scratch[BN * TT * SS];
// bf16-split packed operands (per element 1 u32; pair p -> u32 2p=hi, 2p+1=lo)
__device__ uint32_t g_apk[BN * TT * 768];       // A(out) = concat(c, inputs)
__device__ uint32_t g_wpk[IND * 768];           // Wout
__device__ uint32_t g_wqpk[MD * 512];           // Wq
__device__ uint32_t g_wcpk[MD * 256];           // Wc
__device__ uint32_t g_mpk[BN * SS * 256];       // mems  [row][k=m]  (proj A)
__device__ uint32_t g_mtpk[BN * 256 * 512];     // mems^T [b][m][k=s] (ctx B)
__device__ uint32_t g_ppk[BN * TT * 512];       // P probabilities [row][k=s]

__device__ __forceinline__ float tanhap(float x) {
    float y;
    asm("tanh.approx.f32 %0, %1;" : "=f"(y) : "f"(x));
    return y;
}

__device__ __forceinline__ uint32_t pack_bf2(float x0, float x1) {
    __nv_bfloat162 h = __floats2bfloat162_rn(x0, x1);
    return *reinterpret_cast<uint32_t*>(&h);
}

__device__ __forceinline__ void split2(float x0, float x1,
                                       uint32_t& hi, uint32_t& lo) {
    const float h0 = __bfloat162float(__float2bfloat16_rn(x0));
    const float h1 = __bfloat162float(__float2bfloat16_rn(x1));
    hi = pack_bf2(h0, h1);
    lo = pack_bf2(x0 - h0, x1 - h1);
}

__device__ __forceinline__ void mma_bf(float* cc,
    uint32_t a0, uint32_t a1, uint32_t a2, uint32_t a3,
    uint32_t b0, uint32_t b1)
{
    asm volatile(
        "mma.sync.aligned.m16n8k16.row.col.f32.bf16.bf16.f32 "
        "{%0,%1,%2,%3},{%4,%5,%6,%7},{%8,%9},{%0,%1,%2,%3};"
        : "+f"(cc[0]), "+f"(cc[1]), "+f"(cc[2]), "+f"(cc[3])
        : "r"(a0), "r"(a1), "r"(a2), "r"(a3), "r"(b0), "r"(b1));
}

// ---------------------------------------------------------------------------
// cvt_pre: ALL static packing in one launch (flat-index regions).
// ---------------------------------------------------------------------------
__global__ __launch_bounds__(256) void cvt_pre(
    const float* __restrict__ inputs, const float* __restrict__ mems,
    const float* __restrict__ Wq, const float* __restrict__ Wc,
    const float* __restrict__ Wout)
{
    int idx = blockIdx.x * 256 + threadIdx.x;
    uint32_t hi, lo;
    if (idx < 196608) {                       // R0: Wout
        const int row = idx / 384, p = idx % 384;
        split2(Wout[row * 768 + 2 * p], Wout[row * 768 + 2 * p + 1], hi, lo);
        g_wpk[row * 768 + 2 * p] = hi;
        g_wpk[row * 768 + 2 * p + 1] = lo;
        return;
    }
    idx -= 196608;
    if (idx < 524288) {                       // R1: inputs
        const int row = idx >> 8, q = idx & 255;
        split2(inputs[row * 512 + 2 * q], inputs[row * 512 + 2 * q + 1], hi, lo);
        g_apk[row * 768 + 256 + 2 * q] = hi;
        g_apk[row * 768 + 256 + 2 * q + 1] = lo;
        return;
    }
    idx -= 524288;
    if (idx < 65536) {                        // R2: Wq
        const int row = idx >> 8, p = idx & 255;
        split2(Wq[row * 512 + 2 * p], Wq[row * 512 + 2 * p + 1], hi, lo);
        g_wqpk[row * 512 + 2 * p] = hi;
        g_wqpk[row * 512 + 2 * p + 1] = lo;
        return;
    }
    idx -= 65536;
    if (idx < 32768) {                        // R3: Wc
        const int row = idx >> 7, p = idx & 127;
        split2(Wc[row * 256 + 2 * p], Wc[row * 256 + 2 * p + 1], hi, lo);
        g_wcpk[row * 256 + 2 * p] = hi;
        g_wcpk[row * 256 + 2 * p + 1] = lo;
        return;
    }
    idx -= 32768;
    if (idx < 262144) {                       // R4: mems (proj A layout)
        const int row = idx >> 7, p = idx & 127;
        split2(mems[row * 256 + 2 * p], mems[row * 256 + 2 * p + 1], hi, lo);
        g_mpk[row * 256 + 2 * p] = hi;
        g_mpk[row * 256 + 2 * p + 1] = lo;
        return;
    }
    idx -= 262144;
    {                                         // R5: mems^T (ctx B layout)
        const int b = idx >> 16;
        const int m = (idx >> 8) & 255;
        const int p = idx & 255;
        const float x0 = mems[b * 131072 + (2 * p) * 256 + m];
        const float x1 = mems[b * 131072 + (2 * p + 1) * 256 + m];
        split2(x0, x1, hi, lo);
        g_mtpk[b * 131072 + m * 512 + 2 * p] = hi;
        g_mtpk[b * 131072 + m * 512 + 2 * p + 1] = lo;
    }
}

// ===========================================================================
// Shared 64x64 bf16x3 mma tile machinery (256 thr, 8 warps = 2m x 4n,
// warp tile 32m x 16n, frags c[2 m16][2 n8][4]).  smem pitch 20 u32.
// ===========================================================================
#define MMA_TILE_BODY(ABASE, ASTR, BBASE, BSTR, NIT)                          \
    const int ar0 = tid >> 2, as0 = (tid & 3) * 4;                            \
    uint4 ra0, rb;                                                            \
    auto ldTile = [&](int it) {                                               \
        const int ko = it * 16;                                               \
        ra0 = *(const uint4*)&(ABASE)[(size_t)(bm + ar0) * (ASTR) + ko + as0];\
        rb  = *(const uint4*)&(BBASE)[(size_t)(bn + ar0) * (BSTR) + ko + as0];\
    };                                                                        \
    auto stTile = [&](int bf_) {                                              \
        *(uint4*)&Ash[bf_][ar0 * 20 + as0] = ra0;                             \
        *(uint4*)&Bsh[bf_][ar0 * 20 + as0] = rb;                              \
    };                                                                        \
    ldTile(0);                                                                \
    stTile(0);                                                                \
    __syncthreads();                                                          \
    int buf = 0;                                                              \
    for (int it = 0; it < (NIT); it++) {                                      \
        const bool more = (it + 1 < (NIT));                                   \
        if (more) ldTile(it + 1);                                             \
        const uint32_t* Ab = Ash[buf] + (wm * 32) * 20;                       \
        const uint32_t* Bb = Bsh[buf] + (wn * 16) * 20;                       \
        uint2 af[2][4];                                                       \
        _Pragma("unroll")                                                     \
        for (int m2 = 0; m2 < 2; m2++) {                                      \
            const int r0 = m2 * 16 + g;                                       \
            af[m2][0] = *(const uint2*)&Ab[r0 * 20 + t * 2];                  \
            af[m2][1] = *(const uint2*)&Ab[(r0 + 8) * 20 + t * 2];            \
            af[m2][2] = *(const uint2*)&Ab[r0 * 20 + t * 2 + 8];              \
            af[m2][3] = *(const uint2*)&Ab[(r0 + 8) * 20 + t * 2 + 8];        \
        }                                                                     \
        uint2 bfr[2][2];                                                      \
        _Pragma("unroll")                                                     \
        for (int n2 = 0; n2 < 2; n2++) {                                      \
            const int rn = n2 * 8 + g;                                        \
            bfr[n2][0] = *(const uint2*)&Bb[rn * 20 + t * 2];                 \
            bfr[n2][1] = *(const uint2*)&Bb[rn * 20 + t * 2 + 8];             \
        }                                                                     \
        _Pragma("unroll")                                                     \
        for (int m2 = 0; m2 < 2; m2++)                                        \
            _Pragma("unroll")                                                 \
            for (int n2 = 0; n2 < 2; n2++) {                                  \
                float* cc = c[m2][n2];                                        \
                mma_bf(cc, af[m2][0].x, af[m2][1].x, af[m2][2].x,             \
                       af[m2][3].x, bfr[n2][0].x, bfr[n2][1].x);              \
                mma_bf(cc, af[m2][0].y, af[m2][1].y, af[m2][2].y,             \
                       af[m2][3].y, bfr[n2][0].x, bfr[n2][1].x);              \
                mma_bf(cc, af[m2][0].x, af[m2][1].x, af[m2][2].x,             \
                       af[m2][3].x, bfr[n2][0].y, bfr[n2][1].y);              \
            }                                                                 \
        if (more) stTile(buf ^ 1);                                            \
        __syncthreads();                                                      \
        buf ^= 1;                                                             \
    }

#define MMA_TILE_PREAMBLE                                                     \
    __shared__ uint32_t Ash[2][64 * 20];                                      \
    __shared__ uint32_t Bsh[2][64 * 20];                                      \
    const int tid = threadIdx.x;                                              \
    const int lane = tid & 31;                                                \
    const int warp = tid >> 5;                                                \
    const int wm = warp >> 2, wn = warp & 3;                                  \
    const int g = lane >> 2, t = lane & 3;                                    \
    float c[2][2][4];                                                         \
    _Pragma("unroll")                                                         \
    for (int m2 = 0; m2 < 2; m2++)                                            \
        _Pragma("unroll")                                                     \
        for (int n2 = 0; n2 < 2; n2++)                                        \
            _Pragma("unroll")                                                 \
            for (int q = 0; q < 4; q++) c[m2][n2][q] = 0.f;

// ---------------------------------------------------------------------------
// proj_mma: z=0: g_wq = inputs @ Wq^T (K=512); z=1: g_uht (transposed) + bc.
// Grid (4, 32, 2) = 256 blocks.
// ---------------------------------------------------------------------------
__global__ __launch_bounds__(256) void proj_mma(const float* __restrict__ bc)
{
    MMA_TILE_PREAMBLE
    const int bm = blockIdx.y * 64;
    const int bn = blockIdx.x * 64;
    const int z = blockIdx.z;

    const uint32_t* Abase = z ? g_mpk : (g_apk + 256);
    const int astr = z ? 256 : 768;
    const uint32_t* Bbase = z ? g_wcpk : g_wqpk;
    const int bstr = z ? 256 : 512;
    const int NIT = z ? 16 : 32;

    MMA_TILE_BODY(Abase, astr, Bbase, bstr, NIT)

    if (z == 0) {
#pragma unroll
        for (int m2 = 0; m2 < 2; m2++) {
            const int r0 = bm + wm * 32 + m2 * 16 + g;
#pragma unroll
            for (int n2 = 0; n2 < 2; n2++) {
                const int col = bn + wn * 16 + n2 * 8 + t * 2;
                float* cc = c[m2][n2];
                *(float2*)&g_wq[r0 * MD + col] = make_float2(cc[0], cc[1]);
                *(float2*)&g_wq[(r0 + 8) * MD + col] = make_float2(cc[2], cc[3]);
            }
        }
    } else {
        const int b_ = bm >> 9;
        float* base = g_uht + b_ * (MD * SS);
#pragma unroll
        for (int m2 = 0; m2 < 2; m2++) {
            const int r0 = bm + wm * 32 + m2 * 16 + g;
            const int s0 = r0 & 511, s1 = (r0 + 8) & 511;
#pragma unroll
            for (int n2 = 0; n2 < 2; n2++) {
                const int col = bn + wn * 16 + n2 * 8 + t * 2;
                const float b0v = bc[col], b1v = bc[col + 1];
                float* cc = c[m2][n2];
                base[col * SS + s0] = cc[0] + b0v;
                base[(col + 1) * SS + s0] = cc[1] + b1v;
                base[col * SS + s1] = cc[2] + b0v;
                base[(col + 1) * SS + s1] = cc[3] + b1v;
            }
        }
    }
}

// ---------------------------------------------------------------------------
// align_kernel (f32 tanh, at MUFU roofline): 64-s chunks, 16-t tiles.
// ---------------------------------------------------------------------------
__global__ __launch_bounds__(256) void align_kernel(
    const int* __restrict__ mem_masks, const float* __restrict__ v,
    float* __restrict__ pa)
{
    const int b = blockIdx.z;
    const int t0 = blockIdx.y * 16;
    const int c = blockIdx.x;
    const int len = mem_masks[b];
    if (c * 64 >= len) return;

    extern __shared__ float sh[];
    float* uh_sh = sh;                 // [256 d][64 s]
    float* wq_sh = sh + 256 * 64;      // [16][256]
    float* v_sh  = wq_sh + 16 * 256;   // [256]

    const int tid = threadIdx.x;
    const int lane = tid & 31;
    const int warp = tid >> 5;

    {
        const float* src = g_wq + (b * TT + t0) * MD;
        for (int i = tid; i < (16 * 256) / 4; i += 256)
            *(float4*)&wq_sh[i * 4] = *(const float4*)&src[i * 4];
        if (tid < 64)
            *(float4*)&v_sh[tid * 4] = *(const float4*)&v[tid * 4];
        const float* usrc = g_uht + b * (MD * SS) + c * 64;
        for (int i = tid; i < 256 * 16; i += 256) {
            const int d = i >> 4, g = i & 15;
            *(float4*)&uh_sh[d * 64 + g * 4] =
                *(const float4*)&usrc[d * SS + g * 4];
        }
    }
    __syncthreads();

    const int ta = warp * 2;
    const float* wq0 = wq_sh + ta * 256;
    const float* wq1 = wq0 + 256;
    const int sl = lane * 2;
    float2 a0 = make_float2(0.f, 0.f);
    float2 a1 = make_float2(0.f, 0.f);
#pragma unroll 8
    for (int d = 0; d < 256; d++) {
        float2 u = *(float2*)&uh_sh[d * 64 + sl];
        float w0 = wq0[d], w1 = wq1[d], vd = v_sh[d];
        a0.x += vd * tanhap(u.x + w0);
        a0.y += vd * tanhap(u.y + w0);
        a1.x += vd * tanhap(u.x + w1);
        a1.y += vd * tanhap(u.y + w1);
    }
    const int sg = c * 64 + sl;
    *(float2*)&pa[(b * TT + t0 + ta) * SS + sg] = a0;
    *(float2*)&pa[(b * TT + t0 + ta + 1) * SS + sg] = a1;
}

// ---------------------------------------------------------------------------
// softmax_kernel: warp per t-row; fp32 probs -> pa, packed bf16 hi/lo -> g_ppk.
// ---------------------------------------------------------------------------
__global__ __launch_bounds__(256) void softmax_kernel(
    const int* __restrict__ mem_masks, float* __restrict__ pa)
{
    const int lane = threadIdx.x & 31;
    const int warp = threadIdx.x >> 5;
    const int row = blockIdx.x * 8 + warp;
    const int b = row >> 9;
    const int len = mem_masks[b];
    float* prow = pa + row * SS;
    const float NEG = -CUDART_INF_F;

    float vals[16];
    float mx = NEG;
#pragma unroll
    for (int k = 0; k < 16; k++) {
        const int s = lane + k * 32;
        const float val = (s < len) ? prow[s] : NEG;
        vals[k] = val;
        mx = fmaxf(mx, val);
    }
#pragma unroll
    for (int o = 16; o; o >>= 1) mx = fmaxf(mx, __shfl_xor_sync(~0u, mx, o));
    float sum = 0.f;
#pragma unroll
    for (int k = 0; k < 16; k++) {
        const int s = lane + k * 32;
        const float e = (s < len) ? __expf(vals[k] - mx) : 0.f;
        vals[k] = e;
        sum += e;
    }
#pragma unroll
    for (int o = 16; o; o >>= 1) sum += __shfl_xor_sync(~0u, sum, o);
    const float inv = 1.0f / sum;
#pragma unroll
    for (int k = 0; k < 16; k++) {
        const float p = vals[k] * inv;
        prow[lane + k * 32] = p;
        const float pp = __shfl_xor_sync(~0u, p, 1);
        if ((lane & 1) == 0) {
            uint32_t hi, lo;
            split2(p, pp, hi, lo);
            *(uint2*)&g_ppk[row * 512 + lane + k * 32] = make_uint2(hi, lo);
        }
    }
}

// ---------------------------------------------------------------------------
// ctx_mma: C[t][m] = sum_s P[t][s]*memsT[m][s], K = len-trimmed (<=512).
// Block 32t x 64m, 256 thr (8 warps = 2 t-groups x 4 m-groups, warp tile
// 16x16). Epilogue writes bf16-split packed ctx DIRECTLY into g_apk's
// [0,256) k-region (c0,c1 are an adjacent col pair = one (hi,lo) unit) —
// cvt_c and the g_ctxp round-trip are eliminated.
// Grid (4 m-tiles, 16 t-tiles, 4 b) = 256 blocks.
// ---------------------------------------------------------------------------
__global__ __launch_bounds__(256) void ctx_mma(const int* __restrict__ mem_masks)
{
    __shared__ uint32_t Ash[2][32 * 20];
    __shared__ uint32_t Bsh[2][64 * 20];

    const int tid = threadIdx.x;
    const int lane = tid & 31;
    const int warp = tid >> 5;
    const int wrow = warp >> 2;           // t group (0..1)
    const int wcol = warp & 3;            // m group (0..3)
    const int g = lane >> 2, t = lane & 3;
    const int b = blockIdx.z;
    const int t0 = blockIdx.y * 32;
    const int bn = blockIdx.x * 64;       // m

    const int len = mem_masks[b];
    const int NIT = (len + 15) >> 4;      // len >= 1 guaranteed

    const uint32_t* Abase = g_ppk + (size_t)(b * TT + t0) * 512;
    const uint32_t* Bbase = g_mtpk + (size_t)b * 131072 + (size_t)bn * 512;

    float c[2][4];
#pragma unroll
    for (int n2 = 0; n2 < 2; n2++)
#pragma unroll
        for (int q = 0; q < 4; q++) c[n2][q] = 0.f;

    const int r4 = tid >> 2, s4 = (tid & 3) * 4;

    uint4 ra, rb;
    auto ldTile = [&](int it) {
        const int ko = it * 16;
        if (tid < 128) ra = *(const uint4*)&Abase[(size_t)r4 * 512 + ko + s4];
        rb = *(const uint4*)&Bbase[(size_t)r4 * 512 + ko + s4];
    };
    auto stTile = [&](int bf_) {
        if (tid < 128) *(uint4*)&Ash[bf_][r4 * 20 + s4] = ra;
        *(uint4*)&Bsh[bf_][r4 * 20 + s4] = rb;
    };

    ldTile(0);
    stTile(0);
    __syncthreads();

    int buf = 0;
    for (int it = 0; it < NIT; it++) {
        const bool more = (it + 1 < NIT);
        if (more) ldTile(it + 1);

        const uint32_t* Ab = Ash[buf] + (wrow * 16) * 20;
        const uint32_t* Bb = Bsh[buf] + (wcol * 16) * 20;

        uint2 af[4];
        af[0] = *(const uint2*)&Ab[g * 20 + t * 2];
        af[1] = *(const uint2*)&Ab[(g + 8) * 20 + t * 2];
        af[2] = *(const uint2*)&Ab[g * 20 + t * 2 + 8];
        af[3] = *(const uint2*)&Ab[(g + 8) * 20 + t * 2 + 8];

        uint2 bfr[2][2];
#pragma unroll
        for (int n2 = 0; n2 < 2; n2++) {
            const int rn = n2 * 8 + g;
            bfr[n2][0] = *(const uint2*)&Bb[rn * 20 + t * 2];
            bfr[n2][1] = *(const uint2*)&Bb[rn * 20 + t * 2 + 8];
        }

#pragma unroll
        for (int n2 = 0; n2 < 2; n2++) {
            float* cc = c[n2];
            mma_bf(cc, af[0].x, af[1].x, af[2].x, af[3].x,
                   bfr[n2][0].x, bfr[n2][1].x);
            mma_bf(cc, af[0].y, af[1].y, af[2].y, af[3].y,
                   bfr[n2][0].x, bfr[n2][1].x);
            mma_bf(cc, af[0].x, af[1].x, af[2].x, af[3].x,
                   bfr[n2][0].y, bfr[n2][1].y);
        }

        if (more) stTile(buf ^ 1);
        __syncthreads();
        buf ^= 1;
    }

    // Epilogue: split (c0,c1)/(c2,c3) col-pairs to bf16 hi/lo, write packed.
    const int row0 = b * TT + t0 + wrow * 16 + g;
#pragma unroll
    for (int n2 = 0; n2 < 2; n2++) {
        const int col = bn + wcol * 16 + n2 * 8 + t * 2;   // even
        uint32_t hi, lo;
        split2(c[n2][0], c[n2][1], hi, lo);
        *(uint2*)&g_apk[(size_t)row0 * 768 + col] = make_uint2(hi, lo);
        split2(c[n2][2], c[n2][3], hi, lo);
        *(uint2*)&g_apk[(size_t)(row0 + 8) * 768 + col] = make_uint2(hi, lo);
    }
}

// ---------------------------------------------------------------------------
// out_mma: attn_h = A @ Wout^T + bout. Grid (8, 32) = 256 blocks, 48 iters.
// ---------------------------------------------------------------------------
__global__ __launch_bounds__(256) void out_mma(
    const float* __restrict__ bout, float* __restrict__ out)
{
    MMA_TILE_PREAMBLE
    const int bm = blockIdx.y * 64;
    const int bn = blockIdx.x * 64;

    MMA_TILE_BODY(g_apk, 768, g_wpk, 768, 48)

#pragma unroll
    for (int m2 = 0; m2 < 2; m2++) {
        const int r0 = bm + wm * 32 + m2 * 16 + g;
#pragma unroll
        for (int n2 = 0; n2 < 2; n2++) {
            const int col = bn + wn * 16 + n2 * 8 + t * 2;
            const float2 bb = *(const float2*)&bout[col];
            float* cc = c[m2][n2];
            *(float2*)&out[r0 * IND + col] =
                make_float2(cc[0] + bb.x, cc[1] + bb.y);
            *(float2*)&out[(r0 + 8) * IND + col] =
                make_float2(cc[2] + bb.x, cc[3] + bb.y);
        }
    }
}

// ---------------------------------------------------------------------------
extern "C" void kernel_launch(void* const* d_in, const int* in_sizes, int n_in,
                              void* d_out, int out_size)
{
    const float* inputs    = (const float*)d_in[0];
    const float* mems      = (const float*)d_in[1];
    const int*   mem_masks = (const int*)d_in[2];
    const float* Wq        = (const float*)d_in[3];
    const float* Wc        = (const float*)d_in[4];
    const float* bc        = (const float*)d_in[5];
    const float* v         = (const float*)d_in[6];
    const float* Wout      = (const float*)d_in[7];
    const float* bout      = (const float*)d_in[8];

    float* out = (float*)d_out;
    float* pa;
    if (out_size >= BN * TT * IND + BN * TT * SS) {
        pa = out + BN * TT * IND;  // align written in-place in the output
    } else {
        cudaGetSymbolAddress((void**)&pa, g_align_scratch);
    }

    const size_t SMEM_ALIGN = (size_t)(256 * 64 + 16 * 256 + 256) * sizeof(float);
    cudaFuncSetAttribute(align_kernel,
                         cudaFuncAttributeMaxDynamicSharedMemorySize, (int)SMEM_ALIGN);

    cvt_pre<<<5248, 256>>>(inputs, mems, Wq, Wc, Wout);
    proj_mma<<<dim3(4, 32, 2), 256>>>(bc);
    align_kernel<<<dim3(8, 32, 4), 256, SMEM_ALIGN>>>(mem_masks, v, pa);
    softmax_kernel<<<256, 256>>>(mem_masks, pa);
    ctx_mma<<<dim3(4, 16, 4), 256>>>(mem_masks);
    out_mma<<<dim3(8, 32), 256>>>(bout, out);
}